// round 10
// baseline (speedup 1.0000x reference)
#include <cuda_runtime.h>
#include <cstdint>

#define Bb 256
#define Tt 512
typedef unsigned long long ull;

__device__ uint2 g_keys[1024];
__device__ float g_gum[1024][2560];
__device__ int   g_act2[Tt * Bb];
__device__ float g_gi[(size_t)Bb * Tt * 384];

__device__ __forceinline__ void tf2x32(uint32_t k0, uint32_t k1,
                                       uint32_t x0, uint32_t x1,
                                       uint32_t &o0, uint32_t &o1) {
  uint32_t k2 = k0 ^ k1 ^ 0x1BD11BDAu;
#define R_(r) { x0 += x1; x1 = (x1 << (r)) | (x1 >> (32 - (r))); x1 ^= x0; }
  x0 += k0; x1 += k1;
  R_(13) R_(15) R_(26) R_(6)  x0 += k1; x1 += k2 + 1u;
  R_(17) R_(29) R_(16) R_(24) x0 += k2; x1 += k0 + 2u;
  R_(13) R_(15) R_(26) R_(6)  x0 += k0; x1 += k1 + 3u;
  R_(17) R_(29) R_(16) R_(24) x0 += k1; x1 += k2 + 4u;
  R_(13) R_(15) R_(26) R_(6)  x0 += k2; x1 += k0 + 5u;
#undef R_
  o0 = x0; o1 = x1;
}

__device__ __forceinline__ float b2g(uint32_t bits) {
  float f = __uint_as_float((bits >> 9) | 0x3f800000u) - 1.0f;
  float u = fmaxf(f, 1.17549435e-38f);
  return -logf(-logf(u));
}

__device__ __forceinline__ float sigm(float x) { return 1.0f / (1.0f + expf(-x)); }

__device__ __forceinline__ void f2(ull &c, ull a, ull b) {
  asm("fma.rn.f32x2 %0, %1, %2, %0;" : "+l"(c) : "l"(a), "l"(b));
}
__device__ __forceinline__ float hsum(ull a) {
  return __uint_as_float((unsigned)a) + __uint_as_float((unsigned)(a >> 32));
}

__global__ void k_keys() {
  int j = blockIdx.x * 256 + threadIdx.x;
  if (j >= 1024) return;
  uint32_t o0, o1;
  tf2x32(0u, 42u, 0u, (uint32_t)j, o0, o1);
  g_keys[j] = make_uint2(o0, o1);
}

__global__ void k_gum() {
  int j = blockIdx.x;
  uint2 key = g_keys[j];
  for (int p = threadIdx.x; p < 2560; p += 256) {
    uint32_t o0, o1;
    tf2x32(key.x, key.y, 0u, (uint32_t)p, o0, o1);
    g_gum[j][p] = b2g(o0 ^ o1);
  }
}

// gi GEMM (R8 version): grid (1024,3), 256 thr, 128x128 tile, 8x8 micro-tile.
__global__ __launch_bounds__(256) void k_gi(const float* __restrict__ x,
                                            const float* __restrict__ wih,
                                            const float* __restrict__ bih,
                                            const float* __restrict__ bhh) {
  extern __shared__ float sm[];
  float* xs = sm;
  float* ws = xs + 128 * 132;
  int tid = threadIdx.x;
  size_t m0 = (size_t)blockIdx.x * 128;
  int n0 = blockIdx.y * 128;
  int mr = tid >> 1, hl = tid & 1;
  {
    const float4* src = (const float4*)(x + (m0 + mr) * 128 + hl * 64);
    float4* dst = (float4*)(xs + mr * 132 + hl * 64);
#pragma unroll
    for (int i = 0; i < 16; i++) dst[i] = src[i];
  }
  {
    const float4* src = (const float4*)(wih + (size_t)(n0 + mr) * 128 + hl * 64);
#pragma unroll
    for (int i = 0; i < 16; i++) {
      float4 v = src[i];
      int kb = hl * 64 + i * 4;
      ws[(kb + 0) * 132 + mr] = v.x; ws[(kb + 1) * 132 + mr] = v.y;
      ws[(kb + 2) * 132 + mr] = v.z; ws[(kb + 3) * 132 + mr] = v.w;
    }
  }
  int tx = tid & 15, ty = tid >> 4;
  float bv[8];
#pragma unroll
  for (int j = 0; j < 8; j++) {
    int g = n0 + tx * 8 + j;
    bv[j] = bih[g] + (g < 256 ? bhh[g] : 0.0f);
  }
  __syncthreads();
  float acc[64];
#pragma unroll
  for (int i = 0; i < 8; i++)
#pragma unroll
    for (int j = 0; j < 8; j++) acc[i * 8 + j] = bv[j];
  const float* xrow = xs + ty * 8 * 132;
#pragma unroll 2
  for (int kk = 0; kk < 128; kk += 4) {
    float4 a4[8];
#pragma unroll
    for (int i = 0; i < 8; i++) a4[i] = *(const float4*)(xrow + i * 132 + kk);
#pragma unroll
    for (int dk = 0; dk < 4; dk++) {
      float4 bl = *(const float4*)(ws + (kk + dk) * 132 + tx * 8);
      float4 bh = *(const float4*)(ws + (kk + dk) * 132 + tx * 8 + 4);
#pragma unroll
      for (int i = 0; i < 8; i++) {
        float av = (dk == 0) ? a4[i].x : (dk == 1) ? a4[i].y : (dk == 2) ? a4[i].z : a4[i].w;
        acc[i*8+0] += av * bl.x; acc[i*8+1] += av * bl.y;
        acc[i*8+2] += av * bl.z; acc[i*8+3] += av * bl.w;
        acc[i*8+4] += av * bh.x; acc[i*8+5] += av * bh.y;
        acc[i*8+6] += av * bh.z; acc[i*8+7] += av * bh.w;
      }
    }
  }
#pragma unroll
  for (int i = 0; i < 8; i++) {
    float* dst = g_gi + (m0 + ty * 8 + i) * 384 + n0 + tx * 8;
    *(float4*)(dst)     = make_float4(acc[i*8+0], acc[i*8+1], acc[i*8+2], acc[i*8+3]);
    *(float4*)(dst + 4) = make_float4(acc[i*8+4], acc[i*8+5], acc[i*8+6], acc[i*8+7]);
  }
}

__global__ __launch_bounds__(128) void k_act2(const float* __restrict__ x,
                                              const float* __restrict__ w1,
                                              const float* __restrict__ b1,
                                              const float* __restrict__ w2,
                                              const float* __restrict__ b2) {
  extern __shared__ float sm[];
  float* xs  = sm;
  float* w1s = xs + 128 * 132;
  float* w2s = w1s + 64 * 128;
  float* b1s = w2s + 640;
  float* b2s = b1s + 64;
  int tid = threadIdx.x;
  size_t row0 = (size_t)blockIdx.x * 128;
  const float4* xg = (const float4*)(x + row0 * 128);
  for (int i = tid; i < 128 * 32; i += 128) {
    int r = i >> 5, c = i & 31;
    ((float4*)(xs + r * 132))[c] = xg[i];
  }
  for (int i = tid; i < 64 * 32; i += 128) ((float4*)w1s)[i] = ((const float4*)w1)[i];
  for (int i = tid; i < 640; i += 128) w2s[i] = w2[i];
  if (tid < 64) b1s[tid] = b1[tid];
  if (tid < 10) b2s[tid] = b2[tid];
  __syncthreads();
  float acc[64];
#pragma unroll
  for (int u = 0; u < 64; u++) acc[u] = b1s[u];
  const float4* xr = (const float4*)(xs + tid * 132);
  for (int c = 0; c < 32; c++) {
    float4 xv = xr[c];
#pragma unroll
    for (int u = 0; u < 64; u++) {
      float4 wv = ((const float4*)w1s)[u * 32 + c];
      acc[u] += xv.x * wv.x + xv.y * wv.y + xv.z * wv.z + xv.w * wv.w;
    }
  }
#pragma unroll
  for (int u = 0; u < 64; u++) acc[u] = tanhf(acc[u]);
  size_t row = row0 + tid;
  int b = (int)(row >> 9), t = (int)(row & 511);
  const float* gg = g_gum[2 * t + 1] + b * 10;
  float best = -1e30f; int bi = 0;
#pragma unroll
  for (int a = 0; a < 10; a++) {
    float lg = b2s[a];
#pragma unroll
    for (int u = 0; u < 64; u++) lg += acc[u] * w2s[a * 64 + u];
    float v = lg + gg[a];
    if (v > best) { best = v; bi = a; }
  }
  g_act2[t * 256 + b] = bi;
}

// recurrent v5: 128 CTAs x 640 thr, 2 CTA barriers/step.
// tid<512: GEMV (R8 layout: d=tid&127, q=tid>>7, owners tid<256).
// tid 512..639: 4 logits warps, a1_w1 half-rows in registers.
__global__ __launch_bounds__(640, 1) void k_recur(const int* __restrict__ mask,
                                                  const float* __restrict__ whh,
                                                  const float* __restrict__ bhh,
                                                  const float* __restrict__ a1w1,
                                                  const float* __restrict__ a1b1,
                                                  const float* __restrict__ a1w2,
                                                  const float* __restrict__ a1b2,
                                                  float* __restrict__ out) {
  extern __shared__ float sm[];
  float* wsp  = sm;                   // 256*132 w_hh r,z padded
  float* hs   = wsp + 33792;          // 256
  float* ms   = hs + 256;             // 256
  float* exch = ms + 256;             // 3072
  float* ring = exch + 3072;          // [b2][g3][10][128] = 7680
  float* lgp  = ring + 7680;          // [warp4][20] = 80
  float* gsm  = lgp + 80;             // [2][20]
  float* bsm  = gsm + 40;             // 12
  int*  asm2  = (int*)(bsm + 12);     // [4]
  int*  ais   = asm2 + 4;             // [4]

  int tid = threadIdx.x;
  bool isG = (tid < 512);
  int d = tid & 127, q = (tid >> 7) & 3;
  int bb = q & 1;
  int b0 = blockIdx.x * 2, bg = b0 + bb;
  bool owner = (tid < 256);
  float* outh = out + (size_t)Bb * 128;

  for (int i = tid; i < 256 * 128; i += 640)
    wsp[(i >> 7) * 132 + (i & 127)] = whh[i];
  for (int i = tid; i < 7680; i += 640) ring[i] = 0.0f;
  if (tid < 10) bsm[tid] = a1b2[tid];

  // GEMV regs: n-gate quarter
  ull wn[16];
  if (isG) {
    const ull* src = (const ull*)(whh + (size_t)(256 + d) * 128 + q * 32);
#pragma unroll
    for (int k = 0; k < 16; k++) wn[k] = src[k];
  }
  float bhn = owner ? bhh[256 + d] : 0.0f;

  // logits regs: half-row of a1_w1 (64 floats as 32 ull)
  int lu = 0, lhf = 0, lw = 0, llane = 0;
  ull w1p[32];
  float w2l[10], b1l = 0.0f;
  if (!isG) {
    int lt = tid - 512;
    lw = lt >> 5; llane = lt & 31;
    lhf = llane >> 4;
    lu = lw * 16 + (llane & 15);
    const ull* src = (const ull*)(a1w1 + lu * 128 + lhf * 64);
#pragma unroll
    for (int k = 0; k < 32; k++) w1p[k] = src[k];
    b1l = a1b1[lu];
#pragma unroll
    for (int a = 0; a < 10; a++) w2l[a] = a1w2[a * 64 + lu];
  }

  float h = 0.0f, buf[10];
#pragma unroll
  for (int s9 = 0; s9 < 10; s9++) buf[s9] = 0.0f;

  if (owner) {
    size_t rr = ((size_t)bg * 512) * 384;
    float gir = g_gi[rr + d], giz = g_gi[rr + 128 + d], gin = g_gi[rr + 256 + d];
    float r = sigm(gir), z = sigm(giz);
    h = (1.0f - z) * tanhf(gin + r * bhn);
    outh[((size_t)bg * 512) * 128 + d] = h;
  }
  if (tid >= 480 && tid < 512) {
    int l = tid - 480;
    if (l < 20)      gsm[20 + l] = g_gum[2][(b0 + l / 10) * 10 + l % 10];
    else if (l < 22) asm2[2 + l - 20] = g_act2[256 + b0 + (l - 20)];
  }
  __syncthreads();

  for (int t = 1; t < 512; t++) {
    int cur = t & 1, nxt = cur ^ 1;
    float gir = 0, giz = 0, gin = 0;
    if (owner) {
      size_t rg = ((size_t)bg * 512 + t) * 384;
      gir = g_gi[rg + d]; giz = g_gi[rg + 128 + d]; gin = g_gi[rg + 256 + d];
      float s = h;
#pragma unroll
      for (int s9 = 0; s9 < 9; s9++) { buf[s9] = buf[s9 + 1]; s += buf[s9]; }
      buf[9] = h;
      hs[bb * 128 + d] = h;
      ms[bb * 128 + d] = s * 0.1f;
    }
    __syncthreads();                                // A
    if (isG) {
      // GEMV W@h_{t-1}, f32x2, exch write (R8-identical)
      int k0 = q * 32;
      const ulonglong2* wr2 = (const ulonglong2*)(wsp + d * 132 + k0);
      const ulonglong2* wz2 = (const ulonglong2*)(wsp + (d + 128) * 132 + k0);
      const ulonglong2* va = (const ulonglong2*)(hs + k0);
      const ulonglong2* vb = (const ulonglong2*)(hs + 128 + k0);
      ull ar0 = 0, az0 = 0, an0 = 0, ar1 = 0, az1 = 0, an1 = 0;
#pragma unroll
      for (int c = 0; c < 8; c++) {
        ulonglong2 v0 = va[c], v1 = vb[c];
        ulonglong2 w0 = wr2[c], w1v = wz2[c];
        f2(ar0, w0.x, v0.x); f2(ar0, w0.y, v0.y);
        f2(ar1, w0.x, v1.x); f2(ar1, w0.y, v1.y);
        f2(az0, w1v.x, v0.x); f2(az0, w1v.y, v0.y);
        f2(az1, w1v.x, v1.x); f2(az1, w1v.y, v1.y);
        f2(an0, wn[2*c], v0.x); f2(an0, wn[2*c+1], v0.y);
        f2(an1, wn[2*c], v1.x); f2(an1, wn[2*c+1], v1.y);
      }
      exch[((q * 2 + 0) * 3 + 0) * 128 + d] = hsum(ar0);
      exch[((q * 2 + 0) * 3 + 1) * 128 + d] = hsum(az0);
      exch[((q * 2 + 0) * 3 + 2) * 128 + d] = hsum(an0);
      exch[((q * 2 + 1) * 3 + 0) * 128 + d] = hsum(ar1);
      exch[((q * 2 + 1) * 3 + 1) * 128 + d] = hsum(az1);
      exch[((q * 2 + 1) * 3 + 2) * 128 + d] = hsum(an1);
      if (tid >= 480 && t < 511) {
        int l = tid - 480;
        if (l < 20)
          gsm[nxt * 20 + l] = g_gum[2 * (t + 1)][(b0 + l / 10) * 10 + l % 10];
        else if (l < 22)
          asm2[nxt * 2 + l - 20] = g_act2[(t + 1) * 256 + b0 + (l - 20)];
      }
    } else {
      // logits: z_u half-dots from regs, shfl-combine halves, reduce, argmax
      const ull* mA = (const ull*)ms + lhf * 32;
      const ull* mB = (const ull*)ms + 64 + lhf * 32;
      ull aA0 = 0, aA1 = 0, aB0 = 0, aB1 = 0;
#pragma unroll
      for (int k = 0; k < 32; k += 2) {
        aA0 = aA0; f2(aA0, w1p[k], mA[k]); f2(aA1, w1p[k+1], mA[k+1]);
        f2(aB0, w1p[k], mB[k]); f2(aB1, w1p[k+1], mB[k+1]);
      }
      float pA = hsum(aA0) + hsum(aA1);
      float pB = hsum(aB0) + hsum(aB1);
      pA += __shfl_xor_sync(0xffffffffu, pA, 16);
      pB += __shfl_xor_sync(0xffffffffu, pB, 16);
      float lp[20];
      if (llane < 16) {
        float zA = tanhf(pA + b1l), zB = tanhf(pB + b1l);
#pragma unroll
        for (int a = 0; a < 10; a++) { lp[a] = zA * w2l[a]; lp[10 + a] = zB * w2l[a]; }
      } else {
#pragma unroll
        for (int a = 0; a < 20; a++) lp[a] = 0.0f;
      }
#pragma unroll
      for (int off = 8; off > 0; off >>= 1)
#pragma unroll
        for (int a = 0; a < 20; a++) lp[a] += __shfl_xor_sync(0xffffffffu, lp[a], off);
      if (llane == 0) {
#pragma unroll
        for (int a = 0; a < 20; a++) lgp[lw * 20 + a] = lp[a];
      }
      asm volatile("bar.sync 1, 128;" ::: "memory");
      if (tid < 514) {
        int b = tid - 512;
        float best = -1e30f; int bi = 0;
#pragma unroll
        for (int a = 0; a < 10; a++) {
          float v = lgp[b * 10 + a] + lgp[20 + b * 10 + a]
                  + lgp[40 + b * 10 + a] + lgp[60 + b * 10 + a]
                  + bsm[a] + gsm[cur * 20 + b * 10 + a];
          if (v > best) { best = v; bi = a; }
        }
        ais[b] = bi; ais[2 + b] = asm2[cur * 2 + b];
      }
    }
    __syncthreads();                                // B
    if (owner) {
      int aa = ais[bb], a2i = ais[2 + bb];
      int p9 = (t - 1) % 10, s1 = (t + aa) % 10, s2 = (t + a2i) % 10;
      float fsum[3], wh[3];
#pragma unroll
      for (int g = 0; g < 3; g++) {
        fsum[g] = exch[((0 * 2 + bb) * 3 + g) * 128 + d]
                + exch[((1 * 2 + bb) * 3 + g) * 128 + d]
                + exch[((2 * 2 + bb) * 3 + g) * 128 + d]
                + exch[((3 * 2 + bb) * 3 + g) * 128 + d];
      }
#pragma unroll
      for (int g = 0; g < 3; g++) {
        float v1 = (s1 == p9) ? fsum[g] : ring[((bb * 3 + g) * 10 + s1) * 128 + d];
        float v2 = (s2 == p9) ? fsum[g] : ring[((bb * 3 + g) * 10 + s2) * 128 + d];
        wh[g] = 0.25f * (v1 + v2) + 0.5f * fsum[g];
        ring[((bb * 3 + g) * 10 + p9) * 128 + d] = fsum[g];
      }
      float sa = buf[0], sb2 = buf[0];
#pragma unroll
      for (int s9 = 1; s9 < 10; s9++) {
        if (aa == s9) sa = buf[s9];
        if (a2i == s9) sb2 = buf[s9];
      }
      float wtd = 0.25f * (sa + sb2) + 0.5f * h;
      float r = sigm(gir + wh[0]), z = sigm(giz + wh[1]);
      float n = tanhf(gin + r * (wh[2] + bhn));
      h = (1.0f - z) * n + z * wtd;
      outh[((size_t)bg * 512 + t) * 128 + d] = h;
    }
  }

  __syncthreads();
  if (owner) {
    int cnt = 0;
    for (int t2 = d; t2 < 512; t2 += 128) cnt += mask[bg * 512 + t2];
    exch[tid] = (float)cnt;
  }
  __syncthreads();
  if (tid < 2) {
    int s = 0;
    for (int i = 0; i < 128; i++) s += (int)exch[tid * 128 + i];
    ais[tid] = s - 1;
  }
  __syncthreads();
  if (owner) {
    int li = ais[bb];
    out[bg * 128 + d] = outh[((size_t)bg * 512 + li) * 128 + d];
  }
}

extern "C" void kernel_launch(void* const* d_in, const int* in_sizes, int n_in,
                              void* d_out, int out_size) {
  const float* x    = (const float*)d_in[0];
  const int*   mask = (const int*)d_in[1];
  const float* wih  = (const float*)d_in[2];
  const float* whh  = (const float*)d_in[3];
  const float* bih  = (const float*)d_in[4];
  const float* bhh  = (const float*)d_in[5];
  const float* a1w1 = (const float*)d_in[6];
  const float* a1b1 = (const float*)d_in[7];
  const float* a1w2 = (const float*)d_in[8];
  const float* a1b2 = (const float*)d_in[9];
  const float* a2w1 = (const float*)d_in[10];
  const float* a2b1 = (const float*)d_in[11];
  const float* a2w2 = (const float*)d_in[12];
  const float* a2b2 = (const float*)d_in[13];
  float* out = (float*)d_out;

  const int smem_gi = 2 * 128 * 132 * 4;
  const int smem_a2 = (128 * 132 + 64 * 128 + 640 + 64 + 16) * 4;
  const int smem_rc = (33792 + 256 + 256 + 3072 + 7680 + 80 + 40 + 12) * 4 + 32;

  cudaFuncSetAttribute(k_gi,    cudaFuncAttributeMaxDynamicSharedMemorySize, smem_gi);
  cudaFuncSetAttribute(k_act2,  cudaFuncAttributeMaxDynamicSharedMemorySize, smem_a2);
  cudaFuncSetAttribute(k_recur, cudaFuncAttributeMaxDynamicSharedMemorySize, smem_rc);

  k_keys<<<4, 256>>>();
  k_gum<<<1024, 256>>>();
  k_act2<<<1024, 128, smem_a2>>>(x, a2w1, a2b1, a2w2, a2b2);
  k_gi<<<dim3(1024, 3), 256, smem_gi>>>(x, wih, bih, bhh);
  k_recur<<<128, 640, smem_rc>>>(mask, whh, bhh, a1w1, a1b1, a1w2, a1b2, out);
}

// round 11
// speedup vs baseline: 2.2280x; 2.2280x over previous
#include <cuda_runtime.h>
#include <cstdint>

#define Bb 256
#define Tt 512
typedef unsigned long long ull;

__device__ float g_gum[1024][2560];
__device__ int   g_act2[Tt * Bb];
__device__ float g_gi[(size_t)Bb * Tt * 384];

__device__ __forceinline__ void tf2x32(uint32_t k0, uint32_t k1,
                                       uint32_t x0, uint32_t x1,
                                       uint32_t &o0, uint32_t &o1) {
  uint32_t k2 = k0 ^ k1 ^ 0x1BD11BDAu;
#define R_(r) { x0 += x1; x1 = (x1 << (r)) | (x1 >> (32 - (r))); x1 ^= x0; }
  x0 += k0; x1 += k1;
  R_(13) R_(15) R_(26) R_(6)  x0 += k1; x1 += k2 + 1u;
  R_(17) R_(29) R_(16) R_(24) x0 += k2; x1 += k0 + 2u;
  R_(13) R_(15) R_(26) R_(6)  x0 += k0; x1 += k1 + 3u;
  R_(17) R_(29) R_(16) R_(24) x0 += k1; x1 += k2 + 4u;
  R_(13) R_(15) R_(26) R_(6)  x0 += k2; x1 += k0 + 5u;
#undef R_
  o0 = x0; o1 = x1;
}

__device__ __forceinline__ float b2g(uint32_t bits) {
  float f = __uint_as_float((bits >> 9) | 0x3f800000u) - 1.0f;
  float u = fmaxf(f, 1.17549435e-38f);
  return -logf(-logf(u));
}

__device__ __forceinline__ float sigm(float x) { return 1.0f / (1.0f + expf(-x)); }

__device__ __forceinline__ void f2(ull &c, ull a, ull b) {
  asm("fma.rn.f32x2 %0, %1, %2, %0;" : "+l"(c) : "l"(a), "l"(b));
}
__device__ __forceinline__ float hsum(ull a) {
  return __uint_as_float((unsigned)a) + __uint_as_float((unsigned)(a >> 32));
}

// gumbel noise; each block derives its own split key (k_keys folded in).
__global__ void k_gum() {
  int j = blockIdx.x;
  uint32_t key0, key1;
  {
    uint32_t o0, o1;
    tf2x32(0u, 42u, 0u, (uint32_t)j, o0, o1);
    key0 = o0; key1 = o1;
  }
  for (int p = threadIdx.x; p < 2560; p += 256) {
    uint32_t o0, o1;
    tf2x32(key0, key1, 0u, (uint32_t)p, o0, o1);
    g_gum[j][p] = b2g(o0 ^ o1);
  }
}

// gi GEMM (R8 version): grid (1024,3), 256 thr, 128x128 tile, 8x8 micro-tile.
__global__ __launch_bounds__(256) void k_gi(const float* __restrict__ x,
                                            const float* __restrict__ wih,
                                            const float* __restrict__ bih,
                                            const float* __restrict__ bhh) {
  extern __shared__ float sm[];
  float* xs = sm;
  float* ws = xs + 128 * 132;
  int tid = threadIdx.x;
  size_t m0 = (size_t)blockIdx.x * 128;
  int n0 = blockIdx.y * 128;
  int mr = tid >> 1, hl = tid & 1;
  {
    const float4* src = (const float4*)(x + (m0 + mr) * 128 + hl * 64);
    float4* dst = (float4*)(xs + mr * 132 + hl * 64);
#pragma unroll
    for (int i = 0; i < 16; i++) dst[i] = src[i];
  }
  {
    const float4* src = (const float4*)(wih + (size_t)(n0 + mr) * 128 + hl * 64);
#pragma unroll
    for (int i = 0; i < 16; i++) {
      float4 v = src[i];
      int kb = hl * 64 + i * 4;
      ws[(kb + 0) * 132 + mr] = v.x; ws[(kb + 1) * 132 + mr] = v.y;
      ws[(kb + 2) * 132 + mr] = v.z; ws[(kb + 3) * 132 + mr] = v.w;
    }
  }
  int tx = tid & 15, ty = tid >> 4;
  float bv[8];
#pragma unroll
  for (int j = 0; j < 8; j++) {
    int g = n0 + tx * 8 + j;
    bv[j] = bih[g] + (g < 256 ? bhh[g] : 0.0f);
  }
  __syncthreads();
  float acc[64];
#pragma unroll
  for (int i = 0; i < 8; i++)
#pragma unroll
    for (int j = 0; j < 8; j++) acc[i * 8 + j] = bv[j];
  const float* xrow = xs + ty * 8 * 132;
#pragma unroll 2
  for (int kk = 0; kk < 128; kk += 4) {
    float4 a4[8];
#pragma unroll
    for (int i = 0; i < 8; i++) a4[i] = *(const float4*)(xrow + i * 132 + kk);
#pragma unroll
    for (int dk = 0; dk < 4; dk++) {
      float4 bl = *(const float4*)(ws + (kk + dk) * 132 + tx * 8);
      float4 bh = *(const float4*)(ws + (kk + dk) * 132 + tx * 8 + 4);
#pragma unroll
      for (int i = 0; i < 8; i++) {
        float av = (dk == 0) ? a4[i].x : (dk == 1) ? a4[i].y : (dk == 2) ? a4[i].z : a4[i].w;
        acc[i*8+0] += av * bl.x; acc[i*8+1] += av * bl.y;
        acc[i*8+2] += av * bl.z; acc[i*8+3] += av * bl.w;
        acc[i*8+4] += av * bh.x; acc[i*8+5] += av * bh.y;
        acc[i*8+6] += av * bh.z; acc[i*8+7] += av * bh.w;
      }
    }
  }
#pragma unroll
  for (int i = 0; i < 8; i++) {
    float* dst = g_gi + (m0 + ty * 8 + i) * 384 + n0 + tx * 8;
    *(float4*)(dst)     = make_float4(acc[i*8+0], acc[i*8+1], acc[i*8+2], acc[i*8+3]);
    *(float4*)(dst + 4) = make_float4(acc[i*8+4], acc[i*8+5], acc[i*8+6], acc[i*8+7]);
  }
}

__global__ __launch_bounds__(128) void k_act2(const float* __restrict__ x,
                                              const float* __restrict__ w1,
                                              const float* __restrict__ b1,
                                              const float* __restrict__ w2,
                                              const float* __restrict__ b2) {
  extern __shared__ float sm[];
  float* xs  = sm;
  float* w1s = xs + 128 * 132;
  float* w2s = w1s + 64 * 128;
  float* b1s = w2s + 640;
  float* b2s = b1s + 64;
  int tid = threadIdx.x;
  size_t row0 = (size_t)blockIdx.x * 128;
  const float4* xg = (const float4*)(x + row0 * 128);
  for (int i = tid; i < 128 * 32; i += 128) {
    int r = i >> 5, c = i & 31;
    ((float4*)(xs + r * 132))[c] = xg[i];
  }
  for (int i = tid; i < 64 * 32; i += 128) ((float4*)w1s)[i] = ((const float4*)w1)[i];
  for (int i = tid; i < 640; i += 128) w2s[i] = w2[i];
  if (tid < 64) b1s[tid] = b1[tid];
  if (tid < 10) b2s[tid] = b2[tid];
  __syncthreads();
  float acc[64];
#pragma unroll
  for (int u = 0; u < 64; u++) acc[u] = b1s[u];
  const float4* xr = (const float4*)(xs + tid * 132);
  for (int c = 0; c < 32; c++) {
    float4 xv = xr[c];
#pragma unroll
    for (int u = 0; u < 64; u++) {
      float4 wv = ((const float4*)w1s)[u * 32 + c];
      acc[u] += xv.x * wv.x + xv.y * wv.y + xv.z * wv.z + xv.w * wv.w;
    }
  }
#pragma unroll
  for (int u = 0; u < 64; u++) acc[u] = tanhf(acc[u]);
  size_t row = row0 + tid;
  int b = (int)(row >> 9), t = (int)(row & 511);
  const float* gg = g_gum[2 * t + 1] + b * 10;
  float best = -1e30f; int bi = 0;
#pragma unroll
  for (int a = 0; a < 10; a++) {
    float lg = b2s[a];
#pragma unroll
    for (int u = 0; u < 64; u++) lg += acc[u] * w2s[a * 64 + u];
    float v = lg + gg[a];
    if (v > best) { best = v; bi = a; }
  }
  g_act2[t * 256 + b] = bi;
}

// recurrent (R8 version): 128 CTAs x 512 thr. Wh-ring + f32x2 + n-row-in-regs.
__global__ __launch_bounds__(512, 1) void k_recur(const int* __restrict__ mask,
                                                  const float* __restrict__ whh,
                                                  const float* __restrict__ bhh,
                                                  const float* __restrict__ a1w1,
                                                  const float* __restrict__ a1b1,
                                                  const float* __restrict__ a1w2,
                                                  const float* __restrict__ a1b2,
                                                  float* __restrict__ out) {
  extern __shared__ float sm[];
  float* wsp  = sm;                   // 256*132 (w_hh r,z padded)
  float* hs   = wsp + 256 * 132;      // 256
  float* ms   = hs + 256;             // 256
  float* ps   = ms + 256;             // 512
  float* exch = ps + 512;             // 3072
  float* ring = exch + 3072;          // [b2][g3][10][128] = 7680
  float* w2s  = ring + 7680;          // 640
  float* b1s  = w2s + 640;            // 64
  float* gsm  = b1s + 64;             // [2][20]
  float* bsm  = gsm + 40;             // 12
  int*  asm2  = (int*)(bsm + 12);     // [4]
  int*  ais   = asm2 + 4;             // [4]

  int tid = threadIdx.x;
  int d = tid & 127, q = tid >> 7;
  int wid = tid >> 5, lane = tid & 31;
  int b0 = blockIdx.x * 2;
  int bb = q & 1;
  int bg = b0 + bb;
  bool owner = (tid < 256);
  float* outh = out + (size_t)Bb * 128;

  for (int i = tid; i < 256 * 128; i += 512)
    wsp[(i >> 7) * 132 + (i & 127)] = whh[i];
  for (int i = tid; i < 7680; i += 512) ring[i] = 0.0f;
  for (int i = tid; i < 640; i += 512) w2s[i] = a1w2[i];
  if (tid < 64) b1s[tid] = a1b1[tid];
  if (tid < 10) bsm[tid] = a1b2[tid];

  ull wn[16];
  {
    const ull* src = (const ull*)(whh + (size_t)(256 + d) * 128 + q * 32);
#pragma unroll
    for (int k = 0; k < 16; k++) wn[k] = src[k];
  }
  float w1r[32];
  {
    int u = tid & 63, kq = (tid >> 6) & 3;
    const float4* src = (const float4*)(a1w1 + u * 128 + kq * 32);
#pragma unroll
    for (int k = 0; k < 8; k++) {
      float4 v = src[k];
      w1r[4*k] = v.x; w1r[4*k+1] = v.y; w1r[4*k+2] = v.z; w1r[4*k+3] = v.w;
    }
  }
  float bhn = bhh[256 + d];

  float h = 0.0f, buf[10];
#pragma unroll
  for (int s9 = 0; s9 < 10; s9++) buf[s9] = 0.0f;

  if (owner) {
    size_t rr = ((size_t)bg * 512) * 384;
    float gir = g_gi[rr + d], giz = g_gi[rr + 128 + d], gin = g_gi[rr + 256 + d];
    float r = sigm(gir), z = sigm(giz);
    h = (1.0f - z) * tanhf(gin + r * bhn);
    outh[((size_t)bg * 512) * 128 + d] = h;
  }
  if (tid < 20)       gsm[20 + tid] = g_gum[2][(b0 + tid / 10) * 10 + tid % 10];
  else if (tid < 22)  asm2[2 + tid - 20] = g_act2[256 + b0 + (tid - 20)];
  __syncthreads();

  for (int t = 1; t < 512; t++) {
    int cur = t & 1, nxt = cur ^ 1;
    float gir = 0, giz = 0, gin = 0;
    if (owner) {
      size_t rg = ((size_t)bg * 512 + t) * 384;
      gir = g_gi[rg + d]; giz = g_gi[rg + 128 + d]; gin = g_gi[rg + 256 + d];
      float s = h;
#pragma unroll
      for (int s9 = 0; s9 < 9; s9++) { buf[s9] = buf[s9 + 1]; s += buf[s9]; }
      buf[9] = h;
      hs[bb * 128 + d] = h;
      ms[bb * 128 + d] = s * 0.1f;
    }
    __syncthreads();                                // A
    {
      int k0 = q * 32;
      const ulonglong2* wr2 = (const ulonglong2*)(wsp + d * 132 + k0);
      const ulonglong2* wz2 = (const ulonglong2*)(wsp + (d + 128) * 132 + k0);
      const ulonglong2* va = (const ulonglong2*)(hs + k0);
      const ulonglong2* vb = (const ulonglong2*)(hs + 128 + k0);
      ull ar0 = 0, az0 = 0, an0 = 0, ar1 = 0, az1 = 0, an1 = 0;
#pragma unroll
      for (int c = 0; c < 8; c++) {
        ulonglong2 v0 = va[c], v1 = vb[c];
        ulonglong2 w0 = wr2[c], w1v = wz2[c];
        f2(ar0, w0.x, v0.x); f2(ar0, w0.y, v0.y);
        f2(ar1, w0.x, v1.x); f2(ar1, w0.y, v1.y);
        f2(az0, w1v.x, v0.x); f2(az0, w1v.y, v0.y);
        f2(az1, w1v.x, v1.x); f2(az1, w1v.y, v1.y);
        f2(an0, wn[2*c], v0.x); f2(an0, wn[2*c+1], v0.y);
        f2(an1, wn[2*c], v1.x); f2(an1, wn[2*c+1], v1.y);
      }
      exch[((q * 2 + 0) * 3 + 0) * 128 + d] = hsum(ar0);
      exch[((q * 2 + 0) * 3 + 1) * 128 + d] = hsum(az0);
      exch[((q * 2 + 0) * 3 + 2) * 128 + d] = hsum(an0);
      exch[((q * 2 + 1) * 3 + 0) * 128 + d] = hsum(ar1);
      exch[((q * 2 + 1) * 3 + 1) * 128 + d] = hsum(az1);
      exch[((q * 2 + 1) * 3 + 2) * 128 + d] = hsum(an1);
    }
    {
      int zb = tid >> 8, kq = (tid >> 6) & 3;
      const float4* mv = (const float4*)(ms + zb * 128 + kq * 32);
      float p = 0.0f;
#pragma unroll
      for (int k = 0; k < 8; k++) {
        float4 m = mv[k];
        p += m.x*w1r[4*k] + m.y*w1r[4*k+1] + m.z*w1r[4*k+2] + m.w*w1r[4*k+3];
      }
      ps[tid] = p;
    }
    if (t < 511) {
      if (tid < 20)
        gsm[nxt * 20 + tid] = g_gum[2 * (t + 1)][(b0 + tid / 10) * 10 + tid % 10];
      else if (tid < 22)
        asm2[nxt * 2 + tid - 20] = g_act2[(t + 1) * 256 + b0 + (tid - 20)];
    }
    __syncthreads();                                // B
    if (wid < 2) {
      float sA = 0.0f, sB = 0.0f;
#pragma unroll
      for (int kq = 0; kq < 4; kq++) {
        sA += ps[wid * 256 + kq * 64 + lane];
        sB += ps[wid * 256 + kq * 64 + 32 + lane];
      }
      float zA = tanhf(sA + b1s[lane]), zB = tanhf(sB + b1s[lane + 32]);
      float lp[10];
#pragma unroll
      for (int a = 0; a < 10; a++)
        lp[a] = zA * w2s[a * 64 + lane] + zB * w2s[a * 64 + 32 + lane];
#pragma unroll
      for (int off = 16; off > 0; off >>= 1)
#pragma unroll
        for (int a = 0; a < 10; a++) lp[a] += __shfl_down_sync(0xffffffffu, lp[a], off);
      if (lane == 0) {
        float best = -1e30f; int bi = 0;
#pragma unroll
        for (int a = 0; a < 10; a++) {
          float v = lp[a] + bsm[a] + gsm[cur * 20 + wid * 10 + a];
          if (v > best) { best = v; bi = a; }
        }
        ais[wid] = bi; ais[2 + wid] = asm2[cur * 2 + wid];
      }
    }
    __syncthreads();                                // C
    if (owner) {
      int aa = ais[bb], a2i = ais[2 + bb];
      int p9 = (t - 1) % 10, s1 = (t + aa) % 10, s2 = (t + a2i) % 10;
      float fsum[3], wh[3];
#pragma unroll
      for (int g = 0; g < 3; g++) {
        fsum[g] = exch[((0 * 2 + bb) * 3 + g) * 128 + d]
                + exch[((1 * 2 + bb) * 3 + g) * 128 + d]
                + exch[((2 * 2 + bb) * 3 + g) * 128 + d]
                + exch[((3 * 2 + bb) * 3 + g) * 128 + d];
      }
#pragma unroll
      for (int g = 0; g < 3; g++) {
        float v1 = (s1 == p9) ? fsum[g] : ring[((bb * 3 + g) * 10 + s1) * 128 + d];
        float v2 = (s2 == p9) ? fsum[g] : ring[((bb * 3 + g) * 10 + s2) * 128 + d];
        wh[g] = 0.25f * (v1 + v2) + 0.5f * fsum[g];
        ring[((bb * 3 + g) * 10 + p9) * 128 + d] = fsum[g];
      }
      float sa = buf[0], sb2 = buf[0];
#pragma unroll
      for (int s9 = 1; s9 < 10; s9++) {
        if (aa == s9) sa = buf[s9];
        if (a2i == s9) sb2 = buf[s9];
      }
      float wtd = 0.25f * (sa + sb2) + 0.5f * h;
      float r = sigm(gir + wh[0]), z = sigm(giz + wh[1]);
      float n = tanhf(gin + r * (wh[2] + bhn));
      h = (1.0f - z) * n + z * wtd;
      outh[((size_t)bg * 512 + t) * 128 + d] = h;
    }
  }

  __syncthreads();
  if (owner) {
    int cnt = 0;
    for (int t2 = d; t2 < 512; t2 += 128) cnt += mask[bg * 512 + t2];
    exch[tid] = (float)cnt;
  }
  __syncthreads();
  if (tid < 2) {
    int s = 0;
    for (int i = 0; i < 128; i++) s += (int)exch[tid * 128 + i];
    ais[tid] = s - 1;
  }
  __syncthreads();
  if (owner) {
    int li = ais[bb];
    out[bg * 128 + d] = outh[((size_t)bg * 512 + li) * 128 + d];
  }
}

extern "C" void kernel_launch(void* const* d_in, const int* in_sizes, int n_in,
                              void* d_out, int out_size) {
  const float* x    = (const float*)d_in[0];
  const int*   mask = (const int*)d_in[1];
  const float* wih  = (const float*)d_in[2];
  const float* whh  = (const float*)d_in[3];
  const float* bih  = (const float*)d_in[4];
  const float* bhh  = (const float*)d_in[5];
  const float* a1w1 = (const float*)d_in[6];
  const float* a1b1 = (const float*)d_in[7];
  const float* a1w2 = (const float*)d_in[8];
  const float* a1b2 = (const float*)d_in[9];
  const float* a2w1 = (const float*)d_in[10];
  const float* a2b1 = (const float*)d_in[11];
  const float* a2w2 = (const float*)d_in[12];
  const float* a2b2 = (const float*)d_in[13];
  float* out = (float*)d_out;

  const int smem_gi = 2 * 128 * 132 * 4;
  const int smem_a2 = (128 * 132 + 64 * 128 + 640 + 64 + 16) * 4;
  const int smem_rc = (256 * 132 + 256 + 256 + 512 + 3072 + 7680 + 640 + 64 + 40 + 12) * 4 + 32;

  cudaFuncSetAttribute(k_gi,    cudaFuncAttributeMaxDynamicSharedMemorySize, smem_gi);
  cudaFuncSetAttribute(k_act2,  cudaFuncAttributeMaxDynamicSharedMemorySize, smem_a2);
  cudaFuncSetAttribute(k_recur, cudaFuncAttributeMaxDynamicSharedMemorySize, smem_rc);

  k_gum<<<1024, 256>>>();
  k_act2<<<1024, 128, smem_a2>>>(x, a2w1, a2b1, a2w2, a2b2);
  k_gi<<<dim3(1024, 3), 256, smem_gi>>>(x, wih, bih, bhh);
  k_recur<<<128, 512, smem_rc>>>(mask, whh, bhh, a1w1, a1b1, a1w2, a1b2, out);
}

// round 12
// speedup vs baseline: 2.3039x; 1.0341x over previous
#include <cuda_runtime.h>
#include <cstdint>

#define Bb 256
#define Tt 512
typedef unsigned long long ull;

__device__ float g_gum[1024][2560];
__device__ int   g_act2[Tt * Bb];
__device__ float g_gi[(size_t)Bb * Tt * 384];

__device__ __forceinline__ void tf2x32(uint32_t k0, uint32_t k1,
                                       uint32_t x0, uint32_t x1,
                                       uint32_t &o0, uint32_t &o1) {
  uint32_t k2 = k0 ^ k1 ^ 0x1BD11BDAu;
#define R_(r) { x0 += x1; x1 = (x1 << (r)) | (x1 >> (32 - (r))); x1 ^= x0; }
  x0 += k0; x1 += k1;
  R_(13) R_(15) R_(26) R_(6)  x0 += k1; x1 += k2 + 1u;
  R_(17) R_(29) R_(16) R_(24) x0 += k2; x1 += k0 + 2u;
  R_(13) R_(15) R_(26) R_(6)  x0 += k0; x1 += k1 + 3u;
  R_(17) R_(29) R_(16) R_(24) x0 += k1; x1 += k2 + 4u;
  R_(13) R_(15) R_(26) R_(6)  x0 += k2; x1 += k0 + 5u;
#undef R_
  o0 = x0; o1 = x1;
}

__device__ __forceinline__ float b2g(uint32_t bits) {
  float f = __uint_as_float((bits >> 9) | 0x3f800000u) - 1.0f;
  float u = fmaxf(f, 1.17549435e-38f);
  return -logf(-logf(u));
}

__device__ __forceinline__ float sigm(float x) { return 1.0f / (1.0f + expf(-x)); }

__device__ __forceinline__ void f2(ull &c, ull a, ull b) {
  asm("fma.rn.f32x2 %0, %1, %2, %0;" : "+l"(c) : "l"(a), "l"(b));
}
__device__ __forceinline__ float hsum(ull a) {
  return __uint_as_float((unsigned)a) + __uint_as_float((unsigned)(a >> 32));
}

// gumbel noise; each block derives its own split key.
__global__ void k_gum() {
  int j = blockIdx.x;
  uint32_t key0, key1;
  {
    uint32_t o0, o1;
    tf2x32(0u, 42u, 0u, (uint32_t)j, o0, o1);
    key0 = o0; key1 = o1;
  }
  for (int p = threadIdx.x; p < 2560; p += 256) {
    uint32_t o0, o1;
    tf2x32(key0, key1, 0u, (uint32_t)p, o0, o1);
    g_gum[j][p] = b2g(o0 ^ o1);
  }
}

// gi GEMM: grid (1024,3), 256 thr, 128x128 tile, 8x8 micro-tile.
__global__ __launch_bounds__(256) void k_gi(const float* __restrict__ x,
                                            const float* __restrict__ wih,
                                            const float* __restrict__ bih,
                                            const float* __restrict__ bhh) {
  extern __shared__ float sm[];
  float* xs = sm;
  float* ws = xs + 128 * 132;
  int tid = threadIdx.x;
  size_t m0 = (size_t)blockIdx.x * 128;
  int n0 = blockIdx.y * 128;
  int mr = tid >> 1, hl = tid & 1;
  {
    const float4* src = (const float4*)(x + (m0 + mr) * 128 + hl * 64);
    float4* dst = (float4*)(xs + mr * 132 + hl * 64);
#pragma unroll
    for (int i = 0; i < 16; i++) dst[i] = src[i];
  }
  {
    const float4* src = (const float4*)(wih + (size_t)(n0 + mr) * 128 + hl * 64);
#pragma unroll
    for (int i = 0; i < 16; i++) {
      float4 v = src[i];
      int kb = hl * 64 + i * 4;
      ws[(kb + 0) * 132 + mr] = v.x; ws[(kb + 1) * 132 + mr] = v.y;
      ws[(kb + 2) * 132 + mr] = v.z; ws[(kb + 3) * 132 + mr] = v.w;
    }
  }
  int tx = tid & 15, ty = tid >> 4;
  float bv[8];
#pragma unroll
  for (int j = 0; j < 8; j++) {
    int g = n0 + tx * 8 + j;
    bv[j] = bih[g] + (g < 256 ? bhh[g] : 0.0f);
  }
  __syncthreads();
  float acc[64];
#pragma unroll
  for (int i = 0; i < 8; i++)
#pragma unroll
    for (int j = 0; j < 8; j++) acc[i * 8 + j] = bv[j];
  const float* xrow = xs + ty * 8 * 132;
#pragma unroll 2
  for (int kk = 0; kk < 128; kk += 4) {
    float4 a4[8];
#pragma unroll
    for (int i = 0; i < 8; i++) a4[i] = *(const float4*)(xrow + i * 132 + kk);
#pragma unroll
    for (int dk = 0; dk < 4; dk++) {
      float4 bl = *(const float4*)(ws + (kk + dk) * 132 + tx * 8);
      float4 bh = *(const float4*)(ws + (kk + dk) * 132 + tx * 8 + 4);
#pragma unroll
      for (int i = 0; i < 8; i++) {
        float av = (dk == 0) ? a4[i].x : (dk == 1) ? a4[i].y : (dk == 2) ? a4[i].z : a4[i].w;
        acc[i*8+0] += av * bl.x; acc[i*8+1] += av * bl.y;
        acc[i*8+2] += av * bl.z; acc[i*8+3] += av * bl.w;
        acc[i*8+4] += av * bh.x; acc[i*8+5] += av * bh.y;
        acc[i*8+6] += av * bh.z; acc[i*8+7] += av * bh.w;
      }
    }
  }
#pragma unroll
  for (int i = 0; i < 8; i++) {
    float* dst = g_gi + (m0 + ty * 8 + i) * 384 + n0 + tx * 8;
    *(float4*)(dst)     = make_float4(acc[i*8+0], acc[i*8+1], acc[i*8+2], acc[i*8+3]);
    *(float4*)(dst + 4) = make_float4(acc[i*8+4], acc[i*8+5], acc[i*8+6], acc[i*8+7]);
  }
}

__global__ __launch_bounds__(128) void k_act2(const float* __restrict__ x,
                                              const float* __restrict__ w1,
                                              const float* __restrict__ b1,
                                              const float* __restrict__ w2,
                                              const float* __restrict__ b2) {
  extern __shared__ float sm[];
  float* xs  = sm;
  float* w1s = xs + 128 * 132;
  float* w2s = w1s + 64 * 128;
  float* b1s = w2s + 640;
  float* b2s = b1s + 64;
  int tid = threadIdx.x;
  size_t row0 = (size_t)blockIdx.x * 128;
  const float4* xg = (const float4*)(x + row0 * 128);
  for (int i = tid; i < 128 * 32; i += 128) {
    int r = i >> 5, c = i & 31;
    ((float4*)(xs + r * 132))[c] = xg[i];
  }
  for (int i = tid; i < 64 * 32; i += 128) ((float4*)w1s)[i] = ((const float4*)w1)[i];
  for (int i = tid; i < 640; i += 128) w2s[i] = w2[i];
  if (tid < 64) b1s[tid] = b1[tid];
  if (tid < 10) b2s[tid] = b2[tid];
  __syncthreads();
  float acc[64];
#pragma unroll
  for (int u = 0; u < 64; u++) acc[u] = b1s[u];
  const float4* xr = (const float4*)(xs + tid * 132);
  for (int c = 0; c < 32; c++) {
    float4 xv = xr[c];
#pragma unroll
    for (int u = 0; u < 64; u++) {
      float4 wv = ((const float4*)w1s)[u * 32 + c];
      acc[u] += xv.x * wv.x + xv.y * wv.y + xv.z * wv.z + xv.w * wv.w;
    }
  }
#pragma unroll
  for (int u = 0; u < 64; u++) acc[u] = tanhf(acc[u]);
  size_t row = row0 + tid;
  int b = (int)(row >> 9), t = (int)(row & 511);
  const float* gg = g_gum[2 * t + 1] + b * 10;
  float best = -1e30f; int bi = 0;
#pragma unroll
  for (int a = 0; a < 10; a++) {
    float lg = b2s[a];
#pragma unroll
    for (int u = 0; u < 64; u++) lg += acc[u] * w2s[a * 64 + u];
    float v = lg + gg[a];
    if (v > best) { best = v; bi = a; }
  }
  g_act2[t * 256 + b] = bi;
}

// recurrent v6: 128 CTAs x 512 thr, 2 barriers/step, redundant per-warp argmax.
__global__ __launch_bounds__(512, 1) void k_recur(const int* __restrict__ mask,
                                                  const float* __restrict__ whh,
                                                  const float* __restrict__ bhh,
                                                  const float* __restrict__ a1w1,
                                                  const float* __restrict__ a1b1,
                                                  const float* __restrict__ a1w2,
                                                  const float* __restrict__ a1b2,
                                                  float* __restrict__ out) {
  extern __shared__ float sm[];
  float* wsp  = sm;                   // 256*132 (w_hh r,z padded)
  float* hs   = wsp + 256 * 132;      // 256
  float* ms   = hs + 256;             // 256
  float* ps   = ms + 256;             // 512
  float* exch = ps + 512;             // 3072
  float* ring = exch + 3072;          // [b2][g3][10][128] = 7680
  float* w2s  = ring + 7680;          // 640
  float* b1s  = w2s + 640;            // 64
  float* gsm  = b1s + 64;             // [2][20]
  float* bsm  = gsm + 40;             // 12
  int*  asm2  = (int*)(bsm + 12);     // [2][2] act2 double-buffer
  int*  lix   = asm2 + 4;             // [2] last_idx

  int tid = threadIdx.x;
  int d = tid & 127, q = tid >> 7;
  int lane = tid & 31;
  int b0 = blockIdx.x * 2;
  int bb = q & 1;
  int bg = b0 + bb;
  bool owner = (tid < 256);
  float* outh = out + (size_t)Bb * 128;

  for (int i = tid; i < 256 * 128; i += 512)
    wsp[(i >> 7) * 132 + (i & 127)] = whh[i];
  for (int i = tid; i < 7680; i += 512) ring[i] = 0.0f;
  for (int i = tid; i < 640; i += 512) w2s[i] = a1w2[i];
  if (tid < 64) b1s[tid] = a1b1[tid];
  if (tid < 10) bsm[tid] = a1b2[tid];

  ull wn[16];
  {
    const ull* src = (const ull*)(whh + (size_t)(256 + d) * 128 + q * 32);
#pragma unroll
    for (int k = 0; k < 16; k++) wn[k] = src[k];
  }
  float w1r[32];
  {
    int u = tid & 63, kq = (tid >> 6) & 3;
    const float4* src = (const float4*)(a1w1 + u * 128 + kq * 32);
#pragma unroll
    for (int k = 0; k < 8; k++) {
      float4 v = src[k];
      w1r[4*k] = v.x; w1r[4*k+1] = v.y; w1r[4*k+2] = v.z; w1r[4*k+3] = v.w;
    }
  }
  float bhn = bhh[256 + d];

  float h = 0.0f, buf[10];
#pragma unroll
  for (int s9 = 0; s9 < 10; s9++) buf[s9] = 0.0f;

  if (owner) {
    size_t rr = ((size_t)bg * 512) * 384;
    float gir = g_gi[rr + d], giz = g_gi[rr + 128 + d], gin = g_gi[rr + 256 + d];
    float r = sigm(gir), z = sigm(giz);
    h = (1.0f - z) * tanhf(gin + r * bhn);
    outh[((size_t)bg * 512) * 128 + d] = h;
  }
  if (tid < 20)       gsm[20 + tid] = g_gum[2][(b0 + tid / 10) * 10 + tid % 10];
  else if (tid < 22)  asm2[2 + tid - 20] = g_act2[256 + b0 + (tid - 20)];
  __syncthreads();

  for (int t = 1; t < 512; t++) {
    int cur = t & 1, nxt = cur ^ 1;
    float gir = 0, giz = 0, gin = 0;
    if (owner) {
      size_t rg = ((size_t)bg * 512 + t) * 384;
      gir = g_gi[rg + d]; giz = g_gi[rg + 128 + d]; gin = g_gi[rg + 256 + d];
      float s = h;
#pragma unroll
      for (int s9 = 0; s9 < 9; s9++) { buf[s9] = buf[s9 + 1]; s += buf[s9]; }
      buf[9] = h;
      hs[bb * 128 + d] = h;
      ms[bb * 128 + d] = s * 0.1f;
    }
    __syncthreads();                                // A
    {
      // GEMV W@h_{t-1}, f32x2, exch partials
      int k0 = q * 32;
      const ulonglong2* wr2 = (const ulonglong2*)(wsp + d * 132 + k0);
      const ulonglong2* wz2 = (const ulonglong2*)(wsp + (d + 128) * 132 + k0);
      const ulonglong2* va = (const ulonglong2*)(hs + k0);
      const ulonglong2* vb = (const ulonglong2*)(hs + 128 + k0);
      ull ar0 = 0, az0 = 0, an0 = 0, ar1 = 0, az1 = 0, an1 = 0;
#pragma unroll
      for (int c = 0; c < 8; c++) {
        ulonglong2 v0 = va[c], v1 = vb[c];
        ulonglong2 w0 = wr2[c], w1v = wz2[c];
        f2(ar0, w0.x, v0.x); f2(ar0, w0.y, v0.y);
        f2(ar1, w0.x, v1.x); f2(ar1, w0.y, v1.y);
        f2(az0, w1v.x, v0.x); f2(az0, w1v.y, v0.y);
        f2(az1, w1v.x, v1.x); f2(az1, w1v.y, v1.y);
        f2(an0, wn[2*c], v0.x); f2(an0, wn[2*c+1], v0.y);
        f2(an1, wn[2*c], v1.x); f2(an1, wn[2*c+1], v1.y);
      }
      exch[((q * 2 + 0) * 3 + 0) * 128 + d] = hsum(ar0);
      exch[((q * 2 + 0) * 3 + 1) * 128 + d] = hsum(az0);
      exch[((q * 2 + 0) * 3 + 2) * 128 + d] = hsum(an0);
      exch[((q * 2 + 1) * 3 + 0) * 128 + d] = hsum(ar1);
      exch[((q * 2 + 1) * 3 + 1) * 128 + d] = hsum(az1);
      exch[((q * 2 + 1) * 3 + 2) * 128 + d] = hsum(an1);
    }
    {
      // zarg partial: thread (u, kq, zb)
      int zb = tid >> 8, kq = (tid >> 6) & 3;
      const float4* mv = (const float4*)(ms + zb * 128 + kq * 32);
      float p = 0.0f;
#pragma unroll
      for (int k = 0; k < 8; k++) {
        float4 m = mv[k];
        p += m.x*w1r[4*k] + m.y*w1r[4*k+1] + m.z*w1r[4*k+2] + m.w*w1r[4*k+3];
      }
      ps[tid] = p;
    }
    if (t < 511) {
      if (tid < 20)
        gsm[nxt * 20 + tid] = g_gum[2 * (t + 1)][(b0 + tid / 10) * 10 + tid % 10];
      else if (tid < 22)
        asm2[nxt * 2 + tid - 20] = g_act2[(t + 1) * 256 + b0 + (tid - 20)];
    }
    __syncthreads();                                // B
    if (owner) {
      // redundant logits + argmax: every owner warp, its own batch bb
      int u0 = lane, u1 = lane + 32;
      const float* pb = ps + bb * 256;
      float sA = pb[u0] + pb[64 + u0] + pb[128 + u0] + pb[192 + u0];
      float sB = pb[u1] + pb[64 + u1] + pb[128 + u1] + pb[192 + u1];
      float zA = tanhf(sA + b1s[u0]), zB = tanhf(sB + b1s[u1]);
      float lp[10];
#pragma unroll
      for (int a = 0; a < 10; a++)
        lp[a] = zA * w2s[a * 64 + u0] + zB * w2s[a * 64 + u1];
#pragma unroll
      for (int off = 16; off > 0; off >>= 1)
#pragma unroll
        for (int a = 0; a < 10; a++) lp[a] += __shfl_xor_sync(0xffffffffu, lp[a], off);
      int aa = 0;
      {
        float best = -1e30f;
#pragma unroll
        for (int a = 0; a < 10; a++) {
          float v = lp[a] + bsm[a] + gsm[cur * 20 + bb * 10 + a];
          if (v > best) { best = v; aa = a; }
        }
      }
      int a2i = asm2[cur * 2 + bb];

      // combine
      int p9 = (t - 1) % 10, s1 = (t + aa) % 10, s2 = (t + a2i) % 10;
      float fsum[3], wh[3];
#pragma unroll
      for (int g = 0; g < 3; g++) {
        fsum[g] = exch[((0 * 2 + bb) * 3 + g) * 128 + d]
                + exch[((1 * 2 + bb) * 3 + g) * 128 + d]
                + exch[((2 * 2 + bb) * 3 + g) * 128 + d]
                + exch[((3 * 2 + bb) * 3 + g) * 128 + d];
      }
#pragma unroll
      for (int g = 0; g < 3; g++) {
        float v1 = (s1 == p9) ? fsum[g] : ring[((bb * 3 + g) * 10 + s1) * 128 + d];
        float v2 = (s2 == p9) ? fsum[g] : ring[((bb * 3 + g) * 10 + s2) * 128 + d];
        wh[g] = 0.25f * (v1 + v2) + 0.5f * fsum[g];
        ring[((bb * 3 + g) * 10 + p9) * 128 + d] = fsum[g];
      }
      float sa = buf[0], sb2 = buf[0];
#pragma unroll
      for (int s9 = 1; s9 < 10; s9++) {
        if (aa == s9) sa = buf[s9];
        if (a2i == s9) sb2 = buf[s9];
      }
      float wtd = 0.25f * (sa + sb2) + 0.5f * h;
      float r = sigm(gir + wh[0]), z = sigm(giz + wh[1]);
      float n = tanhf(gin + r * (wh[2] + bhn));
      h = (1.0f - z) * n + z * wtd;
      outh[((size_t)bg * 512 + t) * 128 + d] = h;
    }
  }

  __syncthreads();
  if (owner) {
    int cnt = 0;
    for (int t2 = d; t2 < 512; t2 += 128) cnt += mask[bg * 512 + t2];
    exch[tid] = (float)cnt;
  }
  __syncthreads();
  if (tid < 2) {
    int s = 0;
    for (int i = 0; i < 128; i++) s += (int)exch[tid * 128 + i];
    lix[tid] = s - 1;
  }
  __syncthreads();
  if (owner) {
    int li = lix[bb];
    out[bg * 128 + d] = outh[((size_t)bg * 512 + li) * 128 + d];
  }
}

extern "C" void kernel_launch(void* const* d_in, const int* in_sizes, int n_in,
                              void* d_out, int out_size) {
  const float* x    = (const float*)d_in[0];
  const int*   mask = (const int*)d_in[1];
  const float* wih  = (const float*)d_in[2];
  const float* whh  = (const float*)d_in[3];
  const float* bih  = (const float*)d_in[4];
  const float* bhh  = (const float*)d_in[5];
  const float* a1w1 = (const float*)d_in[6];
  const float* a1b1 = (const float*)d_in[7];
  const float* a1w2 = (const float*)d_in[8];
  const float* a1b2 = (const float*)d_in[9];
  const float* a2w1 = (const float*)d_in[10];
  const float* a2b1 = (const float*)d_in[11];
  const float* a2w2 = (const float*)d_in[12];
  const float* a2b2 = (const float*)d_in[13];
  float* out = (float*)d_out;

  const int smem_gi = 2 * 128 * 132 * 4;
  const int smem_a2 = (128 * 132 + 64 * 128 + 640 + 64 + 16) * 4;
  const int smem_rc = (256 * 132 + 256 + 256 + 512 + 3072 + 7680 + 640 + 64 + 40 + 12) * 4 + 32;

  cudaFuncSetAttribute(k_gi,    cudaFuncAttributeMaxDynamicSharedMemorySize, smem_gi);
  cudaFuncSetAttribute(k_act2,  cudaFuncAttributeMaxDynamicSharedMemorySize, smem_a2);
  cudaFuncSetAttribute(k_recur, cudaFuncAttributeMaxDynamicSharedMemorySize, smem_rc);

  k_gum<<<1024, 256>>>();
  k_act2<<<1024, 128, smem_a2>>>(x, a2w1, a2b1, a2w2, a2b2);
  k_gi<<<dim3(1024, 3), 256, smem_gi>>>(x, wih, bih, bhh);
  k_recur<<<128, 512, smem_rc>>>(mask, whh, bhh, a1w1, a1b1, a1w2, a1b2, out);
}

// round 13
// speedup vs baseline: 2.5368x; 1.1011x over previous
#include <cuda_runtime.h>
#include <cstdint>

#define Bb 256
#define Tt 512
typedef unsigned long long ull;

__device__ float g_gum[1024][2560];
__device__ int   g_act2[Tt * Bb];
__device__ float g_gi[(size_t)Bb * Tt * 384];

__device__ __forceinline__ void tf2x32(uint32_t k0, uint32_t k1,
                                       uint32_t x0, uint32_t x1,
                                       uint32_t &o0, uint32_t &o1) {
  uint32_t k2 = k0 ^ k1 ^ 0x1BD11BDAu;
#define R_(r) { x0 += x1; x1 = (x1 << (r)) | (x1 >> (32 - (r))); x1 ^= x0; }
  x0 += k0; x1 += k1;
  R_(13) R_(15) R_(26) R_(6)  x0 += k1; x1 += k2 + 1u;
  R_(17) R_(29) R_(16) R_(24) x0 += k2; x1 += k0 + 2u;
  R_(13) R_(15) R_(26) R_(6)  x0 += k0; x1 += k1 + 3u;
  R_(17) R_(29) R_(16) R_(24) x0 += k1; x1 += k2 + 4u;
  R_(13) R_(15) R_(26) R_(6)  x0 += k2; x1 += k0 + 5u;
#undef R_
  o0 = x0; o1 = x1;
}

__device__ __forceinline__ float b2g(uint32_t bits) {
  float f = __uint_as_float((bits >> 9) | 0x3f800000u) - 1.0f;
  float u = fmaxf(f, 1.17549435e-38f);
  return -logf(-logf(u));
}

__device__ __forceinline__ float sigm(float x) { return 1.0f / (1.0f + expf(-x)); }

__device__ __forceinline__ void f2(ull &c, ull a, ull b) {
  asm("fma.rn.f32x2 %0, %1, %2, %0;" : "+l"(c) : "l"(a), "l"(b));
}
__device__ __forceinline__ ull addf2(ull a, ull b) {
  ull r; asm("add.rn.f32x2 %0, %1, %2;" : "=l"(r) : "l"(a), "l"(b)); return r;
}
__device__ __forceinline__ ull mulf2(ull a, ull b) {
  ull r; asm("mul.rn.f32x2 %0, %1, %2;" : "=l"(r) : "l"(a), "l"(b)); return r;
}
__device__ __forceinline__ ull fmaf2v(ull a, ull b, ull c) {
  ull r; asm("fma.rn.f32x2 %0, %1, %2, %3;" : "=l"(r) : "l"(a), "l"(b), "l"(c)); return r;
}
__device__ __forceinline__ float hsum(ull a) {
  return __uint_as_float((unsigned)a) + __uint_as_float((unsigned)(a >> 32));
}
__device__ __forceinline__ ull packf2(float lo, float hi) {
  return (ull)__float_as_uint(lo) | ((ull)__float_as_uint(hi) << 32);
}

// gumbel noise; each block derives its own split key.
__global__ void k_gum() {
  int j = blockIdx.x;
  uint32_t key0, key1;
  {
    uint32_t o0, o1;
    tf2x32(0u, 42u, 0u, (uint32_t)j, o0, o1);
    key0 = o0; key1 = o1;
  }
  for (int p = threadIdx.x; p < 2560; p += 256) {
    uint32_t o0, o1;
    tf2x32(key0, key1, 0u, (uint32_t)p, o0, o1);
    g_gum[j][p] = b2g(o0 ^ o1);
  }
}

// gi GEMM: grid (1024,3), 256 thr, 128x128 tile, 8x8 micro-tile.
__global__ __launch_bounds__(256) void k_gi(const float* __restrict__ x,
                                            const float* __restrict__ wih,
                                            const float* __restrict__ bih,
                                            const float* __restrict__ bhh) {
  extern __shared__ float sm[];
  float* xs = sm;
  float* ws = xs + 128 * 132;
  int tid = threadIdx.x;
  size_t m0 = (size_t)blockIdx.x * 128;
  int n0 = blockIdx.y * 128;
  int mr = tid >> 1, hl = tid & 1;
  {
    const float4* src = (const float4*)(x + (m0 + mr) * 128 + hl * 64);
    float4* dst = (float4*)(xs + mr * 132 + hl * 64);
#pragma unroll
    for (int i = 0; i < 16; i++) dst[i] = src[i];
  }
  {
    const float4* src = (const float4*)(wih + (size_t)(n0 + mr) * 128 + hl * 64);
#pragma unroll
    for (int i = 0; i < 16; i++) {
      float4 v = src[i];
      int kb = hl * 64 + i * 4;
      ws[(kb + 0) * 132 + mr] = v.x; ws[(kb + 1) * 132 + mr] = v.y;
      ws[(kb + 2) * 132 + mr] = v.z; ws[(kb + 3) * 132 + mr] = v.w;
    }
  }
  int tx = tid & 15, ty = tid >> 4;
  float bv[8];
#pragma unroll
  for (int j = 0; j < 8; j++) {
    int g = n0 + tx * 8 + j;
    bv[j] = bih[g] + (g < 256 ? bhh[g] : 0.0f);
  }
  __syncthreads();
  float acc[64];
#pragma unroll
  for (int i = 0; i < 8; i++)
#pragma unroll
    for (int j = 0; j < 8; j++) acc[i * 8 + j] = bv[j];
  const float* xrow = xs + ty * 8 * 132;
#pragma unroll 2
  for (int kk = 0; kk < 128; kk += 4) {
    float4 a4[8];
#pragma unroll
    for (int i = 0; i < 8; i++) a4[i] = *(const float4*)(xrow + i * 132 + kk);
#pragma unroll
    for (int dk = 0; dk < 4; dk++) {
      float4 bl = *(const float4*)(ws + (kk + dk) * 132 + tx * 8);
      float4 bh = *(const float4*)(ws + (kk + dk) * 132 + tx * 8 + 4);
#pragma unroll
      for (int i = 0; i < 8; i++) {
        float av = (dk == 0) ? a4[i].x : (dk == 1) ? a4[i].y : (dk == 2) ? a4[i].z : a4[i].w;
        acc[i*8+0] += av * bl.x; acc[i*8+1] += av * bl.y;
        acc[i*8+2] += av * bl.z; acc[i*8+3] += av * bl.w;
        acc[i*8+4] += av * bh.x; acc[i*8+5] += av * bh.y;
        acc[i*8+6] += av * bh.z; acc[i*8+7] += av * bh.w;
      }
    }
  }
#pragma unroll
  for (int i = 0; i < 8; i++) {
    float* dst = g_gi + (m0 + ty * 8 + i) * 384 + n0 + tx * 8;
    *(float4*)(dst)     = make_float4(acc[i*8+0], acc[i*8+1], acc[i*8+2], acc[i*8+3]);
    *(float4*)(dst + 4) = make_float4(acc[i*8+4], acc[i*8+5], acc[i*8+6], acc[i*8+7]);
  }
}

__global__ __launch_bounds__(128) void k_act2(const float* __restrict__ x,
                                              const float* __restrict__ w1,
                                              const float* __restrict__ b1,
                                              const float* __restrict__ w2,
                                              const float* __restrict__ b2) {
  extern __shared__ float sm[];
  float* xs  = sm;
  float* w1s = xs + 128 * 132;
  float* w2s = w1s + 64 * 128;
  float* b1s = w2s + 640;
  float* b2s = b1s + 64;
  int tid = threadIdx.x;
  size_t row0 = (size_t)blockIdx.x * 128;
  const float4* xg = (const float4*)(x + row0 * 128);
  for (int i = tid; i < 128 * 32; i += 128) {
    int r = i >> 5, c = i & 31;
    ((float4*)(xs + r * 132))[c] = xg[i];
  }
  for (int i = tid; i < 64 * 32; i += 128) ((float4*)w1s)[i] = ((const float4*)w1)[i];
  for (int i = tid; i < 640; i += 128) w2s[i] = w2[i];
  if (tid < 64) b1s[tid] = b1[tid];
  if (tid < 10) b2s[tid] = b2[tid];
  __syncthreads();
  float acc[64];
#pragma unroll
  for (int u = 0; u < 64; u++) acc[u] = b1s[u];
  const float4* xr = (const float4*)(xs + tid * 132);
  for (int c = 0; c < 32; c++) {
    float4 xv = xr[c];
#pragma unroll
    for (int u = 0; u < 64; u++) {
      float4 wv = ((const float4*)w1s)[u * 32 + c];
      acc[u] += xv.x * wv.x + xv.y * wv.y + xv.z * wv.z + xv.w * wv.w;
    }
  }
#pragma unroll
  for (int u = 0; u < 64; u++) acc[u] = tanhf(acc[u]);
  size_t row = row0 + tid;
  int b = (int)(row >> 9), t = (int)(row & 511);
  const float* gg = g_gum[2 * t + 1] + b * 10;
  float best = -1e30f; int bi = 0;
#pragma unroll
  for (int a = 0; a < 10; a++) {
    float lg = b2s[a];
#pragma unroll
    for (int u = 0; u < 64; u++) lg += acc[u] * w2s[a * 64 + u];
    float v = lg + gg[a];
    if (v > best) { best = v; bi = a; }
  }
  g_act2[t * 256 + b] = bi;
}

// recurrent v7: 128 CTAs x 512 thr, 2 barriers/step, smem h-ring, packed rz,
// incremental counters/pointers.
__global__ __launch_bounds__(512, 1) void k_recur(const int* __restrict__ mask,
                                                  const float* __restrict__ whh,
                                                  const float* __restrict__ bhh,
                                                  const float* __restrict__ a1w1,
                                                  const float* __restrict__ a1b1,
                                                  const float* __restrict__ a1w2,
                                                  const float* __restrict__ a1b2,
                                                  float* __restrict__ out) {
  extern __shared__ float sm[];
  float* wsp    = sm;                    // 33792: w_hh r,z padded (stride 132)
  ull*   exchRZ = (ull*)(sm + 33792);    // [q4][b2][128] ull   (2048 f)
  ull*   ringRZ = (ull*)(sm + 35840);    // [slot10][b2][128] ull (5120 f)
  float* exchN  = sm + 40960;            // [q4][b2][128]
  float* ringN  = sm + 41984;            // [slot10][b2][128]
  float* hring  = sm + 44544;            // [slot10][b2][128]
  float* ms     = sm + 47104;            // [b2][128]
  float* ps     = sm + 47360;            // [512]
  float* w2s    = sm + 47872;            // 640
  float* b1s    = sm + 48512;            // 64
  float* gsm    = sm + 48576;            // [2][20]
  float* bsm    = sm + 48616;            // 12
  int*   asm2   = (int*)(sm + 48628);    // [2][2]
  int*   lix    = asm2 + 4;              // [2]

  int tid = threadIdx.x;
  int d = tid & 127, q = tid >> 7;
  int lane = tid & 31;
  int b0 = blockIdx.x * 2;
  int bb = q & 1;
  int bg = b0 + bb;
  bool owner = (tid < 256);
  float* outh = out + (size_t)Bb * 128;

  for (int i = tid; i < 256 * 128; i += 512)
    wsp[(i >> 7) * 132 + (i & 127)] = whh[i];
  for (int i = tid; i < 2560; i += 512) {
    ringRZ[i] = 0ull; ringN[i] = 0.0f; hring[i] = 0.0f;
  }
  for (int i = tid; i < 640; i += 512) w2s[i] = a1w2[i];
  if (tid < 64) b1s[tid] = a1b1[tid];
  if (tid < 10) bsm[tid] = a1b2[tid];

  ull wn[16];
  {
    const ull* src = (const ull*)(whh + (size_t)(256 + d) * 128 + q * 32);
#pragma unroll
    for (int k = 0; k < 16; k++) wn[k] = src[k];
  }
  float w1r[32];
  {
    int u = tid & 63, kq = (tid >> 6) & 3;
    const float4* src = (const float4*)(a1w1 + u * 128 + kq * 32);
#pragma unroll
    for (int k = 0; k < 8; k++) {
      float4 v = src[k];
      w1r[4*k] = v.x; w1r[4*k+1] = v.y; w1r[4*k+2] = v.z; w1r[4*k+3] = v.w;
    }
  }
  float bhn = bhh[256 + d];

  float h = 0.0f;
  // t = 0
  if (owner) {
    size_t rr = ((size_t)bg * 512) * 384;
    float gir = g_gi[rr + d], giz = g_gi[rr + 128 + d], gin = g_gi[rr + 256 + d];
    float r = sigm(gir), z = sigm(giz);
    h = (1.0f - z) * tanhf(gin + r * bhn);
    outh[((size_t)bg * 512) * 128 + d] = h;
  }

  // prefetch pointers (warp 15 threads 480..501)
  const float* gptr = 0; const int* aptr = 0;
  if (tid >= 480) {
    int l = tid - 480;
    if (l < 20) {
      int off = (b0 + l / 10) * 10 + l % 10;
      gsm[20 + l] = g_gum[2][off];
      gptr = &g_gum[0][0] + (size_t)4 * 2560 + off;      // row 2*(t+1), t=1
    } else if (l < 22) {
      asm2[2 + (l - 20)] = g_act2[256 + b0 + (l - 20)];
      aptr = g_act2 + 2 * 256 + b0 + (l - 20);
    }
  }
  // incremental pointers for owners
  const float* gp = g_gi + ((size_t)bg * 512 + 1) * 384 + d;
  float* op = outh + ((size_t)bg * 512 + 1) * 128 + d;
  float* hrb = hring + bb * 128 + d;      // slot stride 256
  ull*   rrz = ringRZ + bb * 128 + d;     // slot stride 256
  float* rnb = ringN + bb * 128 + d;
  const ull C025 = packf2(0.25f, 0.25f), C05 = packf2(0.5f, 0.5f);

  int tm1 = 0;   // (t-1) % 10
  int tmod = 1;  // t % 10
  __syncthreads();

  for (int t = 1; t < 512; t++) {
    int cur = t & 1, nxt = cur ^ 1;
    float gir = 0, giz = 0, gin = 0;
    if (owner) {
      gir = gp[0]; giz = gp[128]; gin = gp[256]; gp += 384;
      hrb[tm1 * 256] = h;                 // slot now holds h_{t-1}
      float s = hrb[0];
#pragma unroll
      for (int s9 = 1; s9 < 10; s9++) s += hrb[s9 * 256];
      ms[bb * 128 + d] = s * 0.1f;
    }
    __syncthreads();                                // A
    {
      // GEMV W@h_{t-1}, f32x2; v from hring slot tm1
      int k0 = q * 32;
      const float* hb = hring + tm1 * 256;
      const ulonglong2* wr2 = (const ulonglong2*)(wsp + d * 132 + k0);
      const ulonglong2* wz2 = (const ulonglong2*)(wsp + (d + 128) * 132 + k0);
      const ulonglong2* va = (const ulonglong2*)(hb + k0);
      const ulonglong2* vb = (const ulonglong2*)(hb + 128 + k0);
      ull ar0 = 0, az0 = 0, an0 = 0, ar1 = 0, az1 = 0, an1 = 0;
#pragma unroll
      for (int c = 0; c < 8; c++) {
        ulonglong2 v0 = va[c], v1 = vb[c];
        ulonglong2 w0 = wr2[c], w1v = wz2[c];
        f2(ar0, w0.x, v0.x); f2(ar0, w0.y, v0.y);
        f2(ar1, w0.x, v1.x); f2(ar1, w0.y, v1.y);
        f2(az0, w1v.x, v0.x); f2(az0, w1v.y, v0.y);
        f2(az1, w1v.x, v1.x); f2(az1, w1v.y, v1.y);
        f2(an0, wn[2*c], v0.x); f2(an0, wn[2*c+1], v0.y);
        f2(an1, wn[2*c], v1.x); f2(an1, wn[2*c+1], v1.y);
      }
      exchRZ[(q * 2 + 0) * 128 + d] = packf2(hsum(ar0), hsum(az0));
      exchRZ[(q * 2 + 1) * 128 + d] = packf2(hsum(ar1), hsum(az1));
      exchN[(q * 2 + 0) * 128 + d] = hsum(an0);
      exchN[(q * 2 + 1) * 128 + d] = hsum(an1);
    }
    {
      // zarg partial: thread (u, kq, zb)
      int zb = tid >> 8, kq = (tid >> 6) & 3;
      const float4* mv = (const float4*)(ms + zb * 128 + kq * 32);
      float p = 0.0f;
#pragma unroll
      for (int k = 0; k < 8; k++) {
        float4 m = mv[k];
        p += m.x*w1r[4*k] + m.y*w1r[4*k+1] + m.z*w1r[4*k+2] + m.w*w1r[4*k+3];
      }
      ps[tid] = p;
    }
    if (t < 511) {
      if (gptr) { gsm[nxt * 20 + (tid - 480)] = *gptr; gptr += 5120; }
      else if (aptr) { asm2[nxt * 2 + (tid - 500)] = *aptr; aptr += 256; }
    }
    __syncthreads();                                // B
    if (owner) {
      // redundant logits + argmax (R12-identical)
      int u0 = lane, u1 = lane + 32;
      const float* pb = ps + bb * 256;
      float sA = pb[u0] + pb[64 + u0] + pb[128 + u0] + pb[192 + u0];
      float sB = pb[u1] + pb[64 + u1] + pb[128 + u1] + pb[192 + u1];
      float zA = tanhf(sA + b1s[u0]), zB = tanhf(sB + b1s[u1]);
      float lp[10];
#pragma unroll
      for (int a = 0; a < 10; a++)
        lp[a] = zA * w2s[a * 64 + u0] + zB * w2s[a * 64 + u1];
#pragma unroll
      for (int off = 16; off > 0; off >>= 1)
#pragma unroll
        for (int a = 0; a < 10; a++) lp[a] += __shfl_xor_sync(0xffffffffu, lp[a], off);
      int aa = 0;
      {
        float best = -1e30f;
#pragma unroll
        for (int a = 0; a < 10; a++) {
          float v = lp[a] + bsm[a] + gsm[cur * 20 + bb * 10 + a];
          if (v > best) { best = v; aa = a; }
        }
      }
      int a2i = asm2[cur * 2 + bb];
      int s1 = tmod + aa;  if (s1 >= 10) s1 -= 10;
      int s2 = tmod + a2i; if (s2 >= 10) s2 -= 10;

      // fsum (linear order over q, as before)
      const ull* eb = exchRZ + bb * 128 + d;
      ull frz = addf2(addf2(addf2(eb[0], eb[256]), eb[512]), eb[768]);
      const float* ebn = exchN + bb * 128 + d;
      float fn = ((ebn[0] + ebn[256]) + ebn[512]) + ebn[768];

      ull v1rz = (s1 == tm1) ? frz : rrz[s1 * 256];
      ull v2rz = (s2 == tm1) ? frz : rrz[s2 * 256];
      float v1n = (s1 == tm1) ? fn : rnb[s1 * 256];
      float v2n = (s2 == tm1) ? fn : rnb[s2 * 256];
      ull whrz = fmaf2v(addf2(v1rz, v2rz), C025, mulf2(frz, C05));
      float whn = 0.25f * (v1n + v2n) + 0.5f * fn;
      rrz[tm1 * 256] = frz; rnb[tm1 * 256] = fn;

      float ha1 = hrb[s1 * 256], ha2 = hrb[s2 * 256];
      float wtd = 0.25f * (ha1 + ha2) + 0.5f * h;

      float gr = __uint_as_float((unsigned)whrz);
      float gz = __uint_as_float((unsigned)(whrz >> 32));
      float r = sigm(gir + gr), z = sigm(giz + gz);
      float n = tanhf(gin + r * (whn + bhn));
      h = (1.0f - z) * n + z * wtd;
      *op = h; op += 128;
    }
    tm1 = (tm1 == 9) ? 0 : tm1 + 1;
    tmod = (tmod == 9) ? 0 : tmod + 1;
  }

  __syncthreads();
  if (owner) {
    int cnt = 0;
    for (int t2 = d; t2 < 512; t2 += 128) cnt += mask[bg * 512 + t2];
    ps[tid] = (float)cnt;
  }
  __syncthreads();
  if (tid < 2) {
    int s = 0;
    for (int i = 0; i < 128; i++) s += (int)ps[tid * 128 + i];
    lix[tid] = s - 1;
  }
  __syncthreads();
  if (owner) {
    int li = lix[bb];
    out[bg * 128 + d] = outh[((size_t)bg * 512 + li) * 128 + d];
  }
}

extern "C" void kernel_launch(void* const* d_in, const int* in_sizes, int n_in,
                              void* d_out, int out_size) {
  const float* x    = (const float*)d_in[0];
  const int*   mask = (const int*)d_in[1];
  const float* wih  = (const float*)d_in[2];
  const float* whh  = (const float*)d_in[3];
  const float* bih  = (const float*)d_in[4];
  const float* bhh  = (const float*)d_in[5];
  const float* a1w1 = (const float*)d_in[6];
  const float* a1b1 = (const float*)d_in[7];
  const float* a1w2 = (const float*)d_in[8];
  const float* a1b2 = (const float*)d_in[9];
  const float* a2w1 = (const float*)d_in[10];
  const float* a2b1 = (const float*)d_in[11];
  const float* a2w2 = (const float*)d_in[12];
  const float* a2b2 = (const float*)d_in[13];
  float* out = (float*)d_out;

  const int smem_gi = 2 * 128 * 132 * 4;
  const int smem_a2 = (128 * 132 + 64 * 128 + 640 + 64 + 16) * 4;
  const int smem_rc = 48640 * 4;

  cudaFuncSetAttribute(k_gi,    cudaFuncAttributeMaxDynamicSharedMemorySize, smem_gi);
  cudaFuncSetAttribute(k_act2,  cudaFuncAttributeMaxDynamicSharedMemorySize, smem_a2);
  cudaFuncSetAttribute(k_recur, cudaFuncAttributeMaxDynamicSharedMemorySize, smem_rc);

  k_gum<<<1024, 256>>>();
  k_act2<<<1024, 128, smem_a2>>>(x, a2w1, a2b1, a2w2, a2b2);
  k_gi<<<dim3(1024, 3), 256, smem_gi>>>(x, wih, bih, bhh);
  k_recur<<<128, 512, smem_rc>>>(mask, whh, bhh, a1w1, a1b1, a1w2, a1b2, out);
}